// round 9
// baseline (speedup 1.0000x reference)
#include <cuda_runtime.h>

#define NROWS 8192
#define DIM   512
#define HID   1024

// Scratch (allocation-free: __device__ globals), all 16B-aligned.
__device__ __align__(16) float g_part[128 * DIM];
__device__ __align__(16) float g_s[DIM];
__device__ __align__(16) float g_a1[DIM], g_c1[DIM];
__device__ __align__(16) float g_a2[DIM], g_c2[DIM];
__device__ __align__(16) float g_y[(size_t)NROWS * HID];   // 32 MB fp32

// ---------------- helpers ----------------
__device__ __forceinline__ unsigned packbf(float lo, float hi) {
    unsigned d;
    asm("cvt.rn.bf16x2.f32 %0, %1, %2;" : "=r"(d) : "f"(hi), "f"(lo));
    return d;
}
__device__ __forceinline__ void mma_bf16(float* d, const unsigned* a, const unsigned* b) {
    asm volatile(
        "mma.sync.aligned.m16n8k16.row.col.f32.bf16.bf16.f32 "
        "{%0,%1,%2,%3}, {%4,%5,%6,%7}, {%8,%9}, {%0,%1,%2,%3};"
        : "+f"(d[0]), "+f"(d[1]), "+f"(d[2]), "+f"(d[3])
        : "r"(a[0]), "r"(a[1]), "r"(a[2]), "r"(a[3]), "r"(b[0]), "r"(b[1]));
}

// ---------------- stage 1: column partial sums of h ----------------
__global__ void colsum_kernel(const float* __restrict__ h) {
    int d  = threadIdx.x;
    int r0 = blockIdx.x * 64;
    float s = 0.f;
#pragma unroll 8
    for (int r = 0; r < 64; r++)
        s += h[(size_t)(r0 + r) * DIM + d];
    g_part[blockIdx.x * DIM + d] = s;
}

// ---------------- stage 2: s = colsum(h)@vw + N*vb ----------------
__global__ void prep1_kernel(const float* __restrict__ vw,
                             const float* __restrict__ vb) {
    __shared__ float hs[DIM];
    for (int i = threadIdx.x; i < DIM; i += blockDim.x) {
        float s = 0.f;
#pragma unroll 8
        for (int b = 0; b < 128; b++) s += g_part[b * DIM + i];
        hs[i] = s;
    }
    __syncthreads();
    int d = blockIdx.x * blockDim.x + threadIdx.x;
    float s = 0.f;
#pragma unroll 8
    for (int k = 0; k < DIM; k++) s = fmaf(hs[k], vw[k * DIM + d], s);
    g_s[d] = s + 8192.0f * vb[d];
}

// ---------------- stage 3: t = s@ow+ob; fold bn affines ----------------
__global__ void prep2_kernel(const float* __restrict__ ow, const float* __restrict__ ob,
                             const float* __restrict__ g1, const float* __restrict__ b1,
                             const float* __restrict__ m1, const float* __restrict__ v1,
                             const float* __restrict__ g2, const float* __restrict__ b2,
                             const float* __restrict__ m2, const float* __restrict__ v2) {
    __shared__ float ss[DIM];
    for (int i = threadIdx.x; i < DIM; i += blockDim.x) ss[i] = g_s[i];
    __syncthreads();
    int d = blockIdx.x * blockDim.x + threadIdx.x;
    float t = 0.f;
#pragma unroll 8
    for (int k = 0; k < DIM; k++) t = fmaf(ss[k], ow[k * DIM + d], t);
    t += ob[d];
    float A1 = g1[d] * rsqrtf(v1[d] + 1e-5f);
    g_a1[d] = A1;
    g_c1[d] = (t - m1[d]) * A1 + b1[d];
    float A2 = g2[d] * rsqrtf(v2[d] + 1e-5f);
    g_a2[d] = A2;
    g_c2[d] = b2[d] - m2[d] * A2;
}

// =====================================================================
// bf16 m16n8k16 GEMMs. Block 128x128, BK=32, 8 warps (4x2), warp 32x64.
// SMEM fragment order (bf16x2 words):
//  A tile (128m x 32k): word = ((kstep<<3)+mtile)*128 + lane*4 + wi
//    lane=(g<<2)|tg holds row mtile*16+(wi&1)*8+g, k = kstep*16+(wi>>1)*8+2tg{,+1}
//  B tile (32k x 128n): word = ((kstep<<4)+ntile)*64 + lane*2 + j
//    lane=(g<<2)|tg holds n = ntile*8+g, k = kstep*16+j*8+2tg{,+1}
//  One stage = A 2048 + B 2048 words = 16 KB.
// =====================================================================
#define BF_IDX()                                                              \
    const int ac   = ((tid >> 2) & 1) | (((tid >> 3) & 1) << 1) |             \
                     (((tid >> 4) & 1) << 2);                                 \
    const int arow = (tid & 1) | (((tid >> 5) & 1) << 1) |                    \
                     (((tid >> 6) & 1) << 2) | (((tid >> 1) & 1) << 3) |      \
                     (((tid >> 7) & 1) << 4);                                 \
    const int aws  = (ac >> 2) << 3;                                          \
    const int awb  = (((arow & 7) << 2) | ((ac & 1) << 1)) * 4 +              \
                     ((((ac >> 1) & 1) << 1) | ((arow >> 3) & 1));            \
    const int amt0 = arow >> 4;                                               \
    const int bkp  = (tid & 1) | (((tid >> 1) & 1) << 1) |                    \
                     (((tid >> 2) & 1) << 2) | (((tid >> 6) & 1) << 3);       \
    const int buu  = ((tid >> 3) & 1) | (((tid >> 4) & 1) << 1) |             \
                     (((tid >> 5) & 1) << 2) | (((tid >> 7) & 1) << 3);       \
    const int bks  = (bkp >> 3) << 4;                                         \
    const int bj   = (bkp >> 2) & 1;                                          \
    const int btg  = bkp & 3;

#define BF_LOAD(Ap, ldA, Bp, ldB, k0)                                         \
    _Pragma("unroll")                                                         \
    for (int i = 0; i < 4; i++)                                               \
        pa[i] = *(const float4*)((Ap) + (size_t)(bm + arow + 32 * i) * (ldA) +\
                                 (k0) + ac * 4);                              \
    _Pragma("unroll")                                                         \
    for (int s = 0; s < 2; s++) {                                             \
        int u = buu + (s << 4);                                               \
        const float* bp0 = (Bp) + (size_t)((k0) + bkp * 2) * (ldB) + bn + u * 4; \
        pb0[s] = *(const float4*)bp0;                                         \
        pb1[s] = *(const float4*)(bp0 + (ldB));                               \
    }

#define BF_STORE_A_AFF(dst, k0)                                               \
    {                                                                         \
        float4 av = *(const float4*)(g_a1 + (k0) + ac * 4);                   \
        float4 cv = *(const float4*)(g_c1 + (k0) + ac * 4);                   \
        _Pragma("unroll")                                                     \
        for (int i = 0; i < 4; i++) {                                         \
            int idx = (aws + amt0 + 2 * i) * 128 + awb;                       \
            float x0 = fmaf(pa[i].x, av.x, cv.x);                             \
            float x1 = fmaf(pa[i].y, av.y, cv.y);                             \
            float x2 = fmaf(pa[i].z, av.z, cv.z);                             \
            float x3 = fmaf(pa[i].w, av.w, cv.w);                             \
            (dst)[idx]     = packbf(x0, x1);                                  \
            (dst)[idx + 4] = packbf(x2, x3);                                  \
        }                                                                     \
    }

#define BF_STORE_A_PLAIN(dst)                                                 \
    {                                                                         \
        _Pragma("unroll")                                                     \
        for (int i = 0; i < 4; i++) {                                         \
            int idx = (aws + amt0 + 2 * i) * 128 + awb;                       \
            (dst)[idx]     = packbf(pa[i].x, pa[i].y);                        \
            (dst)[idx + 4] = packbf(pa[i].z, pa[i].w);                        \
        }                                                                     \
    }

#define BF_STORE_B(dst)                                                       \
    _Pragma("unroll")                                                         \
    for (int s = 0; s < 2; s++) {                                             \
        int u = buu + (s << 4);                                               \
        float v0[4] = {pb0[s].x, pb0[s].y, pb0[s].z, pb0[s].w};               \
        float v1[4] = {pb1[s].x, pb1[s].y, pb1[s].z, pb1[s].w};               \
        _Pragma("unroll")                                                     \
        for (int st = 0; st < 4; st++) {                                      \
            int q = (st + u) & 3;                                             \
            int n = u * 4 + q;                                                \
            int idx = (bks + (n >> 3)) * 64 + (((n & 7) << 2) | btg) * 2 + bj;\
            (dst)[idx] = packbf(v0[q], v1[q]);                                \
        }                                                                     \
    }

#define BF_COMPUTE(As_, Bs_)                                                  \
    _Pragma("unroll")                                                         \
    for (int ks = 0; ks < 2; ks++) {                                          \
        unsigned af[2][4], bfr[8][2];                                         \
        _Pragma("unroll")                                                     \
        for (int mt = 0; mt < 2; mt++) {                                      \
            uint4 v = *(const uint4*)&(As_)[((ks << 3) + w_m * 2 + mt) * 128  \
                                            + lane * 4];                      \
            af[mt][0] = v.x; af[mt][1] = v.y; af[mt][2] = v.z; af[mt][3] = v.w; \
        }                                                                     \
        _Pragma("unroll")                                                     \
        for (int nt = 0; nt < 8; nt++) {                                      \
            uint2 v = *(const uint2*)&(Bs_)[((ks << 4) + w_n * 8 + nt) * 64   \
                                            + lane * 2];                      \
            bfr[nt][0] = v.x; bfr[nt][1] = v.y;                               \
        }                                                                     \
        _Pragma("unroll")                                                     \
        for (int mt = 0; mt < 2; mt++)                                        \
            _Pragma("unroll")                                                 \
            for (int nt = 0; nt < 8; nt++)                                    \
                mma_bf16(acc[mt][nt], af[mt], bfr[nt]);                       \
    }

#define GEMM_PRE()                                                            \
    const int tid = threadIdx.x;                                              \
    const int lane = tid & 31, wid = tid >> 5;                                \
    const int w_m = wid & 3, w_n = wid >> 2;                                  \
    const int g = lane >> 2, tg = lane & 3;                                   \
    float acc[2][8][4];                                                       \
    _Pragma("unroll")                                                         \
    for (int mt = 0; mt < 2; mt++)                                            \
        _Pragma("unroll")                                                     \
        for (int nt = 0; nt < 8; nt++)                                        \
            _Pragma("unroll")                                                 \
            for (int q = 0; q < 4; q++) acc[mt][nt][q] = 0.f;

// ---------------- FFN GEMM 1 (double-buffered, R4 skeleton) ----------------
// y = relu((h*a1+c1) @ f1w + f1b).  M=8192, K=512, N=1024.
__global__ __launch_bounds__(256, 2) void ffn1_kernel(
    const float* __restrict__ h, const float* __restrict__ w,
    const float* __restrict__ bias) {
    extern __shared__ unsigned dsm_u[];   // 2 stages x (A 2048 + B 2048)
    const int bm = blockIdx.y * 128;
    const int bn = blockIdx.x * 128;
    GEMM_PRE();
    BF_IDX();

    float4 pa[4], pb0[2], pb1[2];
    BF_LOAD(h, DIM, w, HID, 0);
    BF_STORE_A_AFF(dsm_u, 0);
    BF_STORE_B(dsm_u + 2048);
    __syncthreads();

#pragma unroll 1
    for (int kb = 0; kb < 16; kb++) {
        unsigned* Ac = dsm_u + (kb & 1) * 4096;
        if (kb < 15) { BF_LOAD(h, DIM, w, HID, (kb + 1) * 32); }
        BF_COMPUTE(Ac, Ac + 2048);
        if (kb < 15) {
            unsigned* An = dsm_u + ((kb + 1) & 1) * 4096;
            BF_STORE_A_AFF(An, (kb + 1) * 32);
            BF_STORE_B(An + 2048);
            __syncthreads();
        }
    }
    // ---- epilogue: bias + relu -> g_y (fp32) ----
#pragma unroll
    for (int nt = 0; nt < 8; nt++) {
        int col = bn + w_n * 64 + nt * 8 + 2 * tg;
        float2 bv = *(const float2*)(bias + col);
#pragma unroll
        for (int mt = 0; mt < 2; mt++) {
            int r0 = bm + w_m * 32 + mt * 16 + g;
            float2 o0 = make_float2(fmaxf(acc[mt][nt][0] + bv.x, 0.f),
                                    fmaxf(acc[mt][nt][1] + bv.y, 0.f));
            float2 o1 = make_float2(fmaxf(acc[mt][nt][2] + bv.x, 0.f),
                                    fmaxf(acc[mt][nt][3] + bv.y, 0.f));
            *(float2*)(g_y + (size_t)r0 * HID + col) = o0;
            *(float2*)(g_y + (size_t)(r0 + 8) * HID + col) = o1;
        }
    }
}

// ---------------- FFN GEMM 2 (single-buffered, R3 skeleton) ----------------
// out = ((h*a1+c1) + y@f2w + f2b) * a2 + c2.  M=8192, K=1024, N=512.
__global__ __launch_bounds__(256, 2) void ffn2_kernel(
    const float* __restrict__ h, const float* __restrict__ w,
    const float* __restrict__ bias, float* __restrict__ out) {
    __shared__ __align__(16) unsigned As2[2048];
    __shared__ __align__(16) unsigned Bs2[2048];
    const int bm = blockIdx.y * 128;
    const int bn = blockIdx.x * 128;
    GEMM_PRE();
    BF_IDX();

    float4 pa[4], pb0[2], pb1[2];
#pragma unroll 1
    for (int kb = 0; kb < 32; kb++) {
        BF_LOAD(g_y, HID, w, DIM, kb * 32);
        BF_STORE_A_PLAIN(As2);
        BF_STORE_B(Bs2);
        __syncthreads();
        BF_COMPUTE(As2, Bs2);
        __syncthreads();
    }
    // ---- epilogue: residual (bn1-folded h) + f2b, then bn2 affine ----
#pragma unroll
    for (int nt = 0; nt < 8; nt++) {
        int col = bn + w_n * 64 + nt * 8 + 2 * tg;
        float2 fbv = *(const float2*)(bias + col);
        float2 a1v = *(const float2*)(g_a1 + col);
        float2 c1v = *(const float2*)(g_c1 + col);
        float2 a2v = *(const float2*)(g_a2 + col);
        float2 c2v = *(const float2*)(g_c2 + col);
#pragma unroll
        for (int mt = 0; mt < 2; mt++) {
            int r0 = bm + w_m * 32 + mt * 16 + g;
            float2 h0 = *(const float2*)(h + (size_t)r0 * DIM + col);
            float2 h1 = *(const float2*)(h + (size_t)(r0 + 8) * DIM + col);
            float2 o0, o1;
            o0.x = (fmaf(h0.x, a1v.x, c1v.x) + acc[mt][nt][0] + fbv.x) * a2v.x + c2v.x;
            o0.y = (fmaf(h0.y, a1v.y, c1v.y) + acc[mt][nt][1] + fbv.y) * a2v.y + c2v.y;
            o1.x = (fmaf(h1.x, a1v.x, c1v.x) + acc[mt][nt][2] + fbv.x) * a2v.x + c2v.x;
            o1.y = (fmaf(h1.y, a1v.y, c1v.y) + acc[mt][nt][3] + fbv.y) * a2v.y + c2v.y;
            *(float2*)(out + (size_t)r0 * DIM + col) = o0;
            *(float2*)(out + (size_t)(r0 + 8) * DIM + col) = o1;
        }
    }
}

extern "C" void kernel_launch(void* const* d_in, const int* in_sizes, int n_in,
                              void* d_out, int out_size) {
    // metadata order: A,h,qw,qb,kw,kb,vw,vb,ow,ob,f1w,f1b,f2w,f2b,bn1_*,bn2_*
    const float* h   = (const float*)d_in[1];
    const float* vw  = (const float*)d_in[6];
    const float* vb  = (const float*)d_in[7];
    const float* ow  = (const float*)d_in[8];
    const float* ob  = (const float*)d_in[9];
    const float* f1w = (const float*)d_in[10];
    const float* f1b = (const float*)d_in[11];
    const float* f2w = (const float*)d_in[12];
    const float* f2b = (const float*)d_in[13];
    const float* b1g = (const float*)d_in[14];
    const float* b1b = (const float*)d_in[15];
    const float* b1m = (const float*)d_in[16];
    const float* b1v = (const float*)d_in[17];
    const float* b2g = (const float*)d_in[18];
    const float* b2b = (const float*)d_in[19];
    const float* b2m = (const float*)d_in[20];
    const float* b2v = (const float*)d_in[21];
    float* out = (float*)d_out;

    cudaFuncSetAttribute(ffn1_kernel, cudaFuncAttributeMaxDynamicSharedMemorySize, 32768);

    colsum_kernel<<<128, 512>>>(h);
    prep1_kernel<<<2, 256>>>(vw, vb);
    prep2_kernel<<<2, 256>>>(ow, ob, b1g, b1b, b1m, b1v, b2g, b2b, b2m, b2v);
    dim3 g1(HID / 128, NROWS / 128);   // (8, 64)
    ffn1_kernel<<<g1, 256, 32768>>>(h, f1w, f1b);
    dim3 g2(DIM / 128, NROWS / 128);   // (4, 64)
    ffn2_kernel<<<g2, 256>>>(h, f2w, f2b, out);
}

// round 10
// speedup vs baseline: 1.0665x; 1.0665x over previous
#include <cuda_runtime.h>

#define NROWS 8192
#define DIM   512
#define HID   1024

// Scratch (allocation-free __device__ globals), 16B-aligned.
// RULE (GB300/ATS trap): NEVER pass these as kernel arguments from host code —
// that takes the host shadow symbol's address and writes land in host RAM.
// Always reference them directly inside device code.
__device__ __align__(16) float g_part[128 * DIM];
__device__ __align__(16) float g_s[DIM];
__device__ __align__(16) float g_a1[DIM], g_c1[DIM];
__device__ __align__(16) float g_a2[DIM], g_c2[DIM];
// Fragment-ordered operands (layout == R3-validated smem fragment order):
// A-frag tile (128m x 32k): idx = ((kstep<<3)+mtile)*128 + l*4 + j
//   kstep=cc>>3, mtile=row>>4, l=((row&7)<<2)|(cc&3), j=(((cc>>2)&1)<<1)|((row>>3)&1)
// B-frag tile (128n x 32k): idx = ((kstep<<4)+ntile)*64 + l*2 + j
//   ntile=n>>3, l=((n&7)<<2)|(k&3), j=(k>>2)&1
__device__ __align__(16) float g_x1f[(size_t)NROWS * DIM];   // [mb(64)][kb(16)][4096]
__device__ __align__(16) float g_yf[(size_t)NROWS * HID];    // [mb(64)][kb(32)][4096]
__device__ __align__(16) float g_w1f[(size_t)HID * DIM];     // [nb(8)][kb(16)][4096]
__device__ __align__(16) float g_w2f[(size_t)DIM * HID];     // [nb(4)][kb(32)][4096]

// ---------------- helpers ----------------
__device__ __forceinline__ unsigned tf32r(float x) {
    unsigned r;
    asm("cvt.rna.tf32.f32 %0, %1;" : "=r"(r) : "f"(x));
    return r;
}
__device__ __forceinline__ void mma_tf32(float* d, const unsigned* a, const unsigned* b) {
    asm volatile(
        "mma.sync.aligned.m16n8k8.row.col.f32.tf32.tf32.f32 "
        "{%0,%1,%2,%3}, {%4,%5,%6,%7}, {%8,%9}, {%0,%1,%2,%3};"
        : "+f"(d[0]), "+f"(d[1]), "+f"(d[2]), "+f"(d[3])
        : "r"(a[0]), "r"(a[1]), "r"(a[2]), "r"(a[3]), "r"(b[0]), "r"(b[1]));
}

// ---------------- stage 1: column partial sums of h ----------------
__global__ void colsum_kernel(const float* __restrict__ h) {
    int d  = threadIdx.x;
    int r0 = blockIdx.x * 64;
    float s = 0.f;
#pragma unroll 8
    for (int r = 0; r < 64; r++)
        s += h[(size_t)(r0 + r) * DIM + d];
    g_part[blockIdx.x * DIM + d] = s;
}

// ---------------- stage 2: s = colsum(h)@vw + N*vb ----------------
__global__ void prep1_kernel(const float* __restrict__ vw,
                             const float* __restrict__ vb) {
    __shared__ float hs[DIM];
    for (int i = threadIdx.x; i < DIM; i += blockDim.x) {
        float s = 0.f;
#pragma unroll 8
        for (int b = 0; b < 128; b++) s += g_part[b * DIM + i];
        hs[i] = s;
    }
    __syncthreads();
    int d = blockIdx.x * blockDim.x + threadIdx.x;
    float s = 0.f;
#pragma unroll 8
    for (int k = 0; k < DIM; k++) s = fmaf(hs[k], vw[k * DIM + d], s);
    g_s[d] = s + 8192.0f * vb[d];
}

// ---------------- stage 3: t = s@ow+ob; fold bn affines ----------------
__global__ void prep2_kernel(const float* __restrict__ ow, const float* __restrict__ ob,
                             const float* __restrict__ g1, const float* __restrict__ b1,
                             const float* __restrict__ m1, const float* __restrict__ v1,
                             const float* __restrict__ g2, const float* __restrict__ b2,
                             const float* __restrict__ m2, const float* __restrict__ v2) {
    __shared__ float ss[DIM];
    for (int i = threadIdx.x; i < DIM; i += blockDim.x) ss[i] = g_s[i];
    __syncthreads();
    int d = blockIdx.x * blockDim.x + threadIdx.x;
    float t = 0.f;
#pragma unroll 8
    for (int k = 0; k < DIM; k++) t = fmaf(ss[k], ow[k * DIM + d], t);
    t += ob[d];
    float A1 = g1[d] * rsqrtf(v1[d] + 1e-5f);
    g_a1[d] = A1;
    g_c1[d] = (t - m1[d]) * A1 + b1[d];
    float A2 = g2[d] * rsqrtf(v2[d] + 1e-5f);
    g_a2[d] = A2;
    g_c2[d] = b2[d] - m2[d] * A2;
}

// ---------------- prep: h -> x1 frag tiles (bn1 affine + tf32) ----------------
// grid 1024 = [mb(64)][kb(16)], 256 threads; writes g_x1f (device symbol).
__global__ void prep_x1_frag(const float* __restrict__ h) {
    int mb = blockIdx.x >> 4, kb = blockIdx.x & 15;
    int tid = threadIdx.x, l = tid & 31, w = tid >> 5;
    float* tile = g_x1f + ((size_t)blockIdx.x << 12);
#pragma unroll
    for (int si = 0; si < 4; si++) {
        int s = w + si * 8;                  // 0..31 = (kstep<<3)+mtile
        int kstep = s >> 3, mtile = s & 7;
        unsigned vj[4];
#pragma unroll
        for (int j = 0; j < 4; j++) {
            int row = mtile * 16 + ((j & 1) << 3) + (l >> 2);
            int cc  = kstep * 8 + ((j >> 1) << 2) + (l & 3);
            int m = mb * 128 + row, k = kb * 32 + cc;
            vj[j] = tf32r(fmaf(h[(size_t)m * DIM + k], g_a1[k], g_c1[k]));
        }
        uint4 o; o.x = vj[0]; o.y = vj[1]; o.z = vj[2]; o.w = vj[3];
        *(uint4*)(tile + s * 128 + l * 4) = o;
    }
}

// ---------------- prep: weight [K][N] -> B frag tiles [nb][kb] (tf32) --------
// which=0 -> g_w1f (K=512,N=1024); which=1 -> g_w2f (K=1024,N=512).
// Destination selected IN DEVICE CODE (the R5-R7 bug was passing it from host).
__global__ void wfrag_kernel(const float* __restrict__ src, int K, int N, int which) {
    float* dstbase = which ? g_w2f : g_w1f;
    int KB = K >> 5;
    int nb = blockIdx.x / KB, kb = blockIdx.x % KB;
    int tid = threadIdx.x, l = tid & 31, w = tid >> 5;
    float* tile = dstbase + ((size_t)blockIdx.x << 12);
#pragma unroll
    for (int si = 0; si < 8; si++) {
        int s = w + si * 8;                  // 0..63 = (kstep<<4)+ntile
        int kstep = s >> 4, ntile = s & 15;
        unsigned vj[2];
#pragma unroll
        for (int j = 0; j < 2; j++) {
            int n  = nb * 128 + ntile * 8 + (l >> 2);
            int k  = kb * 32 + kstep * 8 + (j << 2) + (l & 3);
            vj[j] = tf32r(src[(size_t)k * N + n]);
        }
        uint2 o; o.x = vj[0]; o.y = vj[1];
        *(uint2*)(tile + s * 64 + l * 2) = o;
    }
}

// =====================================================================
// Ping-pong tf32 GEMM (R4-validated skeleton):
// LDG next tile to regs -> compute current -> STS next -> one sync.
// Block 128x128, BK=32, 8 warps (4x2), warp tile 32x64.
// Dynamic smem 64KB = 2 stages x (A 16KB + B 16KB). All staging LINEAR.
// =====================================================================
#define LOAD_REGS(kb, Abase, Bbase)                                           \
    {                                                                         \
        const float4* at = (const float4*)((Abase) + ((size_t)(kb) << 12));   \
        const float4* bt = (const float4*)((Bbase) + ((size_t)(kb) << 12));   \
        _Pragma("unroll")                                                     \
        for (int i = 0; i < 4; i++) {                                         \
            pa[i] = at[tid + i * 256];                                        \
            pb[i] = bt[tid + i * 256];                                        \
        }                                                                     \
    }

#define STORE_REGS(sb_)                                                       \
    {                                                                         \
        float4* as_ = (float4*)(sb_);                                         \
        float4* bs_ = (float4*)((sb_) + 4096);                                \
        _Pragma("unroll")                                                     \
        for (int i = 0; i < 4; i++) {                                         \
            as_[tid + i * 256] = pa[i];                                       \
            bs_[tid + i * 256] = pb[i];                                       \
        }                                                                     \
    }

#define COMPUTE_ST(sb_)                                                       \
    {                                                                         \
        const unsigned* As = (const unsigned*)(sb_);                          \
        const unsigned* Bs = As + 4096;                                       \
        _Pragma("unroll")                                                     \
        for (int ks = 0; ks < 4; ks++) {                                      \
            unsigned af[2][4], bf[8][2];                                      \
            _Pragma("unroll")                                                 \
            for (int mt = 0; mt < 2; mt++) {                                  \
                uint4 v = *(const uint4*)&As[((ks << 3) + w_m * 2 + mt) * 128 \
                                             + lane * 4];                     \
                af[mt][0] = v.x; af[mt][1] = v.y;                             \
                af[mt][2] = v.z; af[mt][3] = v.w;                             \
            }                                                                 \
            _Pragma("unroll")                                                 \
            for (int nt = 0; nt < 8; nt++) {                                  \
                uint2 v = *(const uint2*)&Bs[((ks << 4) + w_n * 8 + nt) * 64  \
                                             + lane * 2];                     \
                bf[nt][0] = v.x; bf[nt][1] = v.y;                             \
            }                                                                 \
            _Pragma("unroll")                                                 \
            for (int mt = 0; mt < 2; mt++)                                    \
                _Pragma("unroll")                                             \
                for (int nt = 0; nt < 8; nt++)                                \
                    mma_tf32(acc[mt][nt], af[mt], bf[nt]);                    \
        }                                                                     \
    }

#define GEMM_PRE()                                                            \
    extern __shared__ unsigned dsm_u[];                                       \
    const int tid = threadIdx.x;                                              \
    const int lane = tid & 31, wid = tid >> 5;                                \
    const int w_m = wid & 3, w_n = wid >> 2;                                  \
    const int g = lane >> 2, tg = lane & 3;                                   \
    float acc[2][8][4];                                                       \
    _Pragma("unroll")                                                         \
    for (int mt = 0; mt < 2; mt++)                                            \
        _Pragma("unroll")                                                     \
        for (int nt = 0; nt < 8; nt++)                                        \
            _Pragma("unroll")                                                 \
            for (int q = 0; q < 4; q++) acc[mt][nt][q] = 0.f;

#define GEMM_MAINLOOP(Abase, Bbase, KBT)                                      \
    {                                                                         \
        float4 pa[4], pb[4];                                                  \
        LOAD_REGS(0, Abase, Bbase);                                           \
        STORE_REGS(dsm_u);                                                    \
        __syncthreads();                                                      \
        _Pragma("unroll 1")                                                   \
        for (int kb = 0; kb < (KBT); kb++) {                                  \
            if (kb + 1 < (KBT)) LOAD_REGS(kb + 1, Abase, Bbase);              \
            COMPUTE_ST(dsm_u + (kb & 1) * 8192);                              \
            if (kb + 1 < (KBT)) {                                             \
                STORE_REGS(dsm_u + ((kb + 1) & 1) * 8192);                    \
                __syncthreads();                                              \
            }                                                                 \
        }                                                                     \
    }

// ---------------- FFN GEMM 1: yf = tf32(relu(x1 @ w1 + f1b)) (frag store) ----
__global__ __launch_bounds__(256, 2) void ffn1_kernel(const float* __restrict__ bias) {
    GEMM_PRE();
    const float* Ab = g_x1f + (((size_t)blockIdx.y * 16) << 12);   // mb*16 tiles
    const float* Bb = g_w1f + (((size_t)blockIdx.x * 16) << 12);   // nb*16 tiles
    GEMM_MAINLOOP(Ab, Bb, 16);
    const int bn = blockIdx.x * 128;
#pragma unroll
    for (int mt = 0; mt < 2; mt++)
#pragma unroll
        for (int nt = 0; nt < 8; nt++) {
            int col0 = bn + w_n * 64 + nt * 8 + 2 * tg;
            float b0 = bias[col0], b1 = bias[col0 + 1];
#pragma unroll
            for (int q = 0; q < 4; q++) {
                int row = w_m * 32 + mt * 16 + g + ((q >> 1) << 3); // local m
                int col = col0 + (q & 1);                            // global k
                float v = fmaxf(acc[mt][nt][q] + ((q & 1) ? b1 : b0), 0.f);
                int kb = col >> 5, cc = col & 31;
                int kstep = cc >> 3, mtile = row >> 4;
                int l = ((row & 7) << 2) | (cc & 3);
                int j = (((cc >> 2) & 1) << 1) | ((row >> 3) & 1);
                g_yf[(((size_t)blockIdx.y * 32 + kb) << 12) +
                     ((kstep << 3) + mtile) * 128 + l * 4 + j] =
                    __uint_as_float(tf32r(v));
            }
        }
}

// ---------------- FFN GEMM 2 + residual + bn2 (row-major out) ----------------
__global__ __launch_bounds__(256, 2) void ffn2_kernel(
    const float* __restrict__ h, const float* __restrict__ bias,
    float* __restrict__ out) {
    GEMM_PRE();
    const float* Ab = g_yf  + (((size_t)blockIdx.y * 32) << 12);   // mb*32 tiles
    const float* Bb = g_w2f + (((size_t)blockIdx.x * 32) << 12);   // nb*32 tiles
    GEMM_MAINLOOP(Ab, Bb, 32);
    const int bm = blockIdx.y * 128;
    const int bn = blockIdx.x * 128;
#pragma unroll
    for (int nt = 0; nt < 8; nt++) {
        int col = bn + w_n * 64 + nt * 8 + 2 * tg;
        float2 fbv = *(const float2*)(bias + col);
        float2 a1v = *(const float2*)(g_a1 + col);
        float2 c1v = *(const float2*)(g_c1 + col);
        float2 a2v = *(const float2*)(g_a2 + col);
        float2 c2v = *(const float2*)(g_c2 + col);
#pragma unroll
        for (int mt = 0; mt < 2; mt++) {
            int r0 = bm + w_m * 32 + mt * 16 + g;
            float2 h0 = *(const float2*)(h + (size_t)r0 * DIM + col);
            float2 h1 = *(const float2*)(h + (size_t)(r0 + 8) * DIM + col);
            float2 o0, o1;
            o0.x = (fmaf(h0.x, a1v.x, c1v.x) + acc[mt][nt][0] + fbv.x) * a2v.x + c2v.x;
            o0.y = (fmaf(h0.y, a1v.y, c1v.y) + acc[mt][nt][1] + fbv.y) * a2v.y + c2v.y;
            o1.x = (fmaf(h1.x, a1v.x, c1v.x) + acc[mt][nt][2] + fbv.x) * a2v.x + c2v.x;
            o1.y = (fmaf(h1.y, a1v.y, c1v.y) + acc[mt][nt][3] + fbv.y) * a2v.y + c2v.y;
            *(float2*)(out + (size_t)r0 * DIM + col) = o0;
            *(float2*)(out + (size_t)(r0 + 8) * DIM + col) = o1;
        }
    }
}

extern "C" void kernel_launch(void* const* d_in, const int* in_sizes, int n_in,
                              void* d_out, int out_size) {
    // metadata order: A,h,qw,qb,kw,kb,vw,vb,ow,ob,f1w,f1b,f2w,f2b,bn1_*,bn2_*
    const float* h   = (const float*)d_in[1];
    const float* vw  = (const float*)d_in[6];
    const float* vb  = (const float*)d_in[7];
    const float* ow  = (const float*)d_in[8];
    const float* ob  = (const float*)d_in[9];
    const float* f1w = (const float*)d_in[10];
    const float* f1b = (const float*)d_in[11];
    const float* f2w = (const float*)d_in[12];
    const float* f2b = (const float*)d_in[13];
    const float* b1g = (const float*)d_in[14];
    const float* b1b = (const float*)d_in[15];
    const float* b1m = (const float*)d_in[16];
    const float* b1v = (const float*)d_in[17];
    const float* b2g = (const float*)d_in[18];
    const float* b2b = (const float*)d_in[19];
    const float* b2m = (const float*)d_in[20];
    const float* b2v = (const float*)d_in[21];
    float* out = (float*)d_out;

    cudaFuncSetAttribute(ffn1_kernel, cudaFuncAttributeMaxDynamicSharedMemorySize, 65536);
    cudaFuncSetAttribute(ffn2_kernel, cudaFuncAttributeMaxDynamicSharedMemorySize, 65536);

    colsum_kernel<<<128, 512>>>(h);
    prep1_kernel<<<2, 256>>>(vw, vb);
    prep2_kernel<<<2, 256>>>(ow, ob, b1g, b1b, b1m, b1v, b2g, b2b, b2m, b2v);
    prep_x1_frag<<<1024, 256>>>(h);
    wfrag_kernel<<<128, 256>>>(f1w, DIM, HID, 0);   // -> g_w1f
    wfrag_kernel<<<128, 256>>>(f2w, HID, DIM, 1);   // -> g_w2f
    dim3 g1(HID / 128, NROWS / 128);   // (8, 64)
    ffn1_kernel<<<g1, 256, 65536>>>(f1b);
    dim3 g2(DIM / 128, NROWS / 128);   // (4, 64)
    ffn2_kernel<<<g2, 256, 65536>>>(h, f2b, out);
}

// round 11
// speedup vs baseline: 1.1745x; 1.1012x over previous
#include <cuda_runtime.h>

#define NROWS 8192
#define DIM   512
#define HID   1024

// Scratch (allocation-free __device__ globals), 16B-aligned.
// RULE (GB300/ATS trap): NEVER pass these as kernel arguments from host code.
__device__ __align__(16) float g_part[128 * DIM];
__device__ __align__(16) float g_s[DIM];
__device__ __align__(16) float g_a1[DIM], g_c1[DIM];
__device__ __align__(16) float g_a2[DIM], g_c2[DIM];
// Fragment-ordered operands (VALIDATED R10, rel_err fingerprint 9.342721e-05):
// A-frag tile (128m x 32k): idx = ((kstep<<3)+mtile)*128 + l*4 + j
//   kstep=cc>>3, mtile=row>>4, l=((row&7)<<2)|(cc&3), j=(((cc>>2)&1)<<1)|((row>>3)&1)
// B-frag tile (128n x 32k): idx = ((kstep<<4)+ntile)*64 + l*2 + j
//   ntile=n>>3, l=((n&7)<<2)|(k&3), j=(k>>2)&1
__device__ __align__(16) float g_x1f[(size_t)NROWS * DIM];   // [mb(64)][kb(16)][4096]
__device__ __align__(16) float g_yf[(size_t)NROWS * HID];    // [mb(64)][kb(32)][4096]
__device__ __align__(16) float g_w1f[(size_t)HID * DIM];     // [nb(8)][kb(16)][4096]
__device__ __align__(16) float g_w2f[(size_t)DIM * HID];     // [nb(4)][kb(32)][4096]

// ---------------- helpers ----------------
__device__ __forceinline__ unsigned tf32r(float x) {
    unsigned r;
    asm("cvt.rna.tf32.f32 %0, %1;" : "=r"(r) : "f"(x));
    return r;
}
__device__ __forceinline__ void mma_tf32(float* d, const unsigned* a, const unsigned* b) {
    asm volatile(
        "mma.sync.aligned.m16n8k8.row.col.f32.tf32.tf32.f32 "
        "{%0,%1,%2,%3}, {%4,%5,%6,%7}, {%8,%9}, {%0,%1,%2,%3};"
        : "+f"(d[0]), "+f"(d[1]), "+f"(d[2]), "+f"(d[3])
        : "r"(a[0]), "r"(a[1]), "r"(a[2]), "r"(a[3]), "r"(b[0]), "r"(b[1]));
}
__device__ __forceinline__ void cp16(unsigned dst, const void* src) {
    asm volatile("cp.async.cg.shared.global [%0], [%1], 16;" :: "r"(dst), "l"(src));
}
#define CP_COMMIT()  asm volatile("cp.async.commit_group;")
#define CP_WAIT1()   asm volatile("cp.async.wait_group 1;" ::: "memory")

// ---------------- stage 1: column partial sums of h ----------------
__global__ void colsum_kernel(const float* __restrict__ h) {
    int d  = threadIdx.x;
    int r0 = blockIdx.x * 64;
    float s = 0.f;
#pragma unroll 8
    for (int r = 0; r < 64; r++)
        s += h[(size_t)(r0 + r) * DIM + d];
    g_part[blockIdx.x * DIM + d] = s;
}

// ---------------- stage 2: s = colsum(h)@vw + N*vb ----------------
__global__ void prep1_kernel(const float* __restrict__ vw,
                             const float* __restrict__ vb) {
    __shared__ float hs[DIM];
    for (int i = threadIdx.x; i < DIM; i += blockDim.x) {
        float s = 0.f;
#pragma unroll 8
        for (int b = 0; b < 128; b++) s += g_part[b * DIM + i];
        hs[i] = s;
    }
    __syncthreads();
    int d = blockIdx.x * blockDim.x + threadIdx.x;
    float s = 0.f;
#pragma unroll 8
    for (int k = 0; k < DIM; k++) s = fmaf(hs[k], vw[k * DIM + d], s);
    g_s[d] = s + 8192.0f * vb[d];
}

// ---------------- stage 3: t = s@ow+ob; fold bn affines ----------------
__global__ void prep2_kernel(const float* __restrict__ ow, const float* __restrict__ ob,
                             const float* __restrict__ g1, const float* __restrict__ b1,
                             const float* __restrict__ m1, const float* __restrict__ v1,
                             const float* __restrict__ g2, const float* __restrict__ b2,
                             const float* __restrict__ m2, const float* __restrict__ v2) {
    __shared__ float ss[DIM];
    for (int i = threadIdx.x; i < DIM; i += blockDim.x) ss[i] = g_s[i];
    __syncthreads();
    int d = blockIdx.x * blockDim.x + threadIdx.x;
    float t = 0.f;
#pragma unroll 8
    for (int k = 0; k < DIM; k++) t = fmaf(ss[k], ow[k * DIM + d], t);
    t += ob[d];
    float A1 = g1[d] * rsqrtf(v1[d] + 1e-5f);
    g_a1[d] = A1;
    g_c1[d] = (t - m1[d]) * A1 + b1[d];
    float A2 = g2[d] * rsqrtf(v2[d] + 1e-5f);
    g_a2[d] = A2;
    g_c2[d] = b2[d] - m2[d] * A2;
}

// ---------------- prep: h -> x1 frag tiles (bn1 affine + tf32) ----------------
__global__ void prep_x1_frag(const float* __restrict__ h) {
    int mb = blockIdx.x >> 4, kb = blockIdx.x & 15;
    int tid = threadIdx.x, l = tid & 31, w = tid >> 5;
    float* tile = g_x1f + ((size_t)blockIdx.x << 12);
#pragma unroll
    for (int si = 0; si < 4; si++) {
        int s = w + si * 8;                  // 0..31 = (kstep<<3)+mtile
        int kstep = s >> 3, mtile = s & 7;
        unsigned vj[4];
#pragma unroll
        for (int j = 0; j < 4; j++) {
            int row = mtile * 16 + ((j & 1) << 3) + (l >> 2);
            int cc  = kstep * 8 + ((j >> 1) << 2) + (l & 3);
            int m = mb * 128 + row, k = kb * 32 + cc;
            vj[j] = tf32r(fmaf(h[(size_t)m * DIM + k], g_a1[k], g_c1[k]));
        }
        uint4 o; o.x = vj[0]; o.y = vj[1]; o.z = vj[2]; o.w = vj[3];
        *(uint4*)(tile + s * 128 + l * 4) = o;
    }
}

// ---------------- prep: weight [K][N] -> B frag tiles [nb][kb] (tf32) --------
// which=0 -> g_w1f; which=1 -> g_w2f. Destination selected IN DEVICE CODE.
__global__ void wfrag_kernel(const float* __restrict__ src, int K, int N, int which) {
    float* dstbase = which ? g_w2f : g_w1f;
    int KB = K >> 5;
    int nb = blockIdx.x / KB, kb = blockIdx.x % KB;
    int tid = threadIdx.x, l = tid & 31, w = tid >> 5;
    float* tile = dstbase + ((size_t)blockIdx.x << 12);
#pragma unroll
    for (int si = 0; si < 8; si++) {
        int s = w + si * 8;                  // 0..63 = (kstep<<4)+ntile
        int kstep = s >> 4, ntile = s & 15;
        unsigned vj[2];
#pragma unroll
        for (int j = 0; j < 2; j++) {
            int n  = nb * 128 + ntile * 8 + (l >> 2);
            int k  = kb * 32 + kstep * 8 + (j << 2) + (l & 3);
            vj[j] = tf32r(src[(size_t)k * N + n]);
        }
        uint2 o; o.x = vj[0]; o.y = vj[1];
        *(uint2*)(tile + s * 64 + l * 2) = o;
    }
}

// =====================================================================
// 3-stage cp.async tf32 GEMM, 64x64 warp tiles.
// CTA 128x128, BK=32, 128 threads = 4 warps (2x2), warp tile 64x64.
// Stage = A 16KB + B 16KB; 3 stages = 96KB dynamic smem. Linear staging.
// =====================================================================
#define STAGE_CP(st, kb, Abase, Bbase)                                        \
    {                                                                         \
        unsigned sb = smem_base + (unsigned)(st) * 32768u;                    \
        const float* at = (Abase) + ((size_t)(kb) << 12);                     \
        const float* bt = (Bbase) + ((size_t)(kb) << 12);                     \
        _Pragma("unroll")                                                     \
        for (int i = 0; i < 8; i++) {                                         \
            int ch = tid + i * 128;                                           \
            cp16(sb + ch * 16, at + ch * 4);                                  \
            cp16(sb + 16384u + ch * 16, bt + ch * 4);                         \
        }                                                                     \
    }

#define COMPUTE_ST(st)                                                        \
    {                                                                         \
        const unsigned* As = dsm_u + (unsigned)(st) * 8192u;                  \
        const unsigned* Bs = As + 4096u;                                      \
        _Pragma("unroll")                                                     \
        for (int ks = 0; ks < 4; ks++) {                                      \
            unsigned af[4][4], bf[8][2];                                      \
            _Pragma("unroll")                                                 \
            for (int mt = 0; mt < 4; mt++) {                                  \
                uint4 v = *(const uint4*)&As[((ks << 3) + w_m * 4 + mt) * 128 \
                                             + lane * 4];                     \
                af[mt][0] = v.x; af[mt][1] = v.y;                             \
                af[mt][2] = v.z; af[mt][3] = v.w;                             \
            }                                                                 \
            _Pragma("unroll")                                                 \
            for (int nt = 0; nt < 8; nt++) {                                  \
                uint2 v = *(const uint2*)&Bs[((ks << 4) + w_n * 8 + nt) * 64  \
                                             + lane * 2];                     \
                bf[nt][0] = v.x; bf[nt][1] = v.y;                             \
            }                                                                 \
            _Pragma("unroll")                                                 \
            for (int mt = 0; mt < 4; mt++)                                    \
                _Pragma("unroll")                                             \
                for (int nt = 0; nt < 8; nt++)                                \
                    mma_tf32(acc[mt][nt], af[mt], bf[nt]);                    \
        }                                                                     \
    }

#define GEMM_PRE()                                                            \
    extern __shared__ unsigned dsm_u[];                                       \
    unsigned smem_base = (unsigned)__cvta_generic_to_shared(dsm_u);           \
    const int tid = threadIdx.x;                                              \
    const int lane = tid & 31, wid = tid >> 5;                                \
    const int w_m = wid & 1, w_n = wid >> 1;                                  \
    const int g = lane >> 2, tg = lane & 3;                                   \
    float acc[4][8][4];                                                       \
    _Pragma("unroll")                                                         \
    for (int mt = 0; mt < 4; mt++)                                            \
        _Pragma("unroll")                                                     \
        for (int nt = 0; nt < 8; nt++)                                        \
            _Pragma("unroll")                                                 \
            for (int q = 0; q < 4; q++) acc[mt][nt][q] = 0.f;

#define GEMM_MAINLOOP(Abase, Bbase, KBT)                                      \
    {                                                                         \
        STAGE_CP(0, 0, Abase, Bbase); CP_COMMIT();                            \
        STAGE_CP(1, 1, Abase, Bbase); CP_COMMIT();                            \
        CP_WAIT1(); __syncthreads();                                          \
        _Pragma("unroll 1")                                                   \
        for (int kb = 0; kb < (KBT); kb++) {                                  \
            if (kb + 2 < (KBT)) { STAGE_CP((kb + 2) % 3, kb + 2, Abase, Bbase); } \
            CP_COMMIT();                                                      \
            COMPUTE_ST(kb % 3);                                               \
            CP_WAIT1(); __syncthreads();                                      \
        }                                                                     \
    }

// ---------------- FFN GEMM 1: yf = tf32(relu(x1 @ w1 + f1b)) (frag store) ----
__global__ __launch_bounds__(128) void ffn1_kernel(const float* __restrict__ bias) {
    GEMM_PRE();
    const float* Ab = g_x1f + (((size_t)blockIdx.y * 16) << 12);   // mb*16 tiles
    const float* Bb = g_w1f + (((size_t)blockIdx.x * 16) << 12);   // nb*16 tiles
    GEMM_MAINLOOP(Ab, Bb, 16);
    const int bn = blockIdx.x * 128;
#pragma unroll
    for (int mt = 0; mt < 4; mt++)
#pragma unroll
        for (int nt = 0; nt < 8; nt++) {
            int col0 = bn + w_n * 64 + nt * 8 + 2 * tg;
            float b0 = bias[col0], b1 = bias[col0 + 1];
#pragma unroll
            for (int q = 0; q < 4; q++) {
                int row = w_m * 64 + mt * 16 + g + ((q >> 1) << 3); // local m
                int col = col0 + (q & 1);                            // global k
                float v = fmaxf(acc[mt][nt][q] + ((q & 1) ? b1 : b0), 0.f);
                int kb = col >> 5, cc = col & 31;
                int kstep = cc >> 3, mtile = row >> 4;
                int l = ((row & 7) << 2) | (cc & 3);
                int j = (((cc >> 2) & 1) << 1) | ((row >> 3) & 1);
                g_yf[(((size_t)blockIdx.y * 32 + kb) << 12) +
                     ((kstep << 3) + mtile) * 128 + l * 4 + j] =
                    __uint_as_float(tf32r(v));
            }
        }
}

// ---------------- FFN GEMM 2 + residual + bn2 (row-major out) ----------------
__global__ __launch_bounds__(128) void ffn2_kernel(
    const float* __restrict__ h, const float* __restrict__ bias,
    float* __restrict__ out) {
    GEMM_PRE();
    const float* Ab = g_yf  + (((size_t)blockIdx.y * 32) << 12);   // mb*32 tiles
    const float* Bb = g_w2f + (((size_t)blockIdx.x * 32) << 12);   // nb*32 tiles
    GEMM_MAINLOOP(Ab, Bb, 32);
    const int bm = blockIdx.y * 128;
    const int bn = blockIdx.x * 128;
#pragma unroll
    for (int nt = 0; nt < 8; nt++) {
        int col = bn + w_n * 64 + nt * 8 + 2 * tg;
        float2 fbv = *(const float2*)(bias + col);
        float2 a1v = *(const float2*)(g_a1 + col);
        float2 c1v = *(const float2*)(g_c1 + col);
        float2 a2v = *(const float2*)(g_a2 + col);
        float2 c2v = *(const float2*)(g_c2 + col);
#pragma unroll
        for (int mt = 0; mt < 4; mt++) {
            int r0 = bm + w_m * 64 + mt * 16 + g;
            float2 h0 = *(const float2*)(h + (size_t)r0 * DIM + col);
            float2 h1 = *(const float2*)(h + (size_t)(r0 + 8) * DIM + col);
            float2 o0, o1;
            o0.x = (fmaf(h0.x, a1v.x, c1v.x) + acc[mt][nt][0] + fbv.x) * a2v.x + c2v.x;
            o0.y = (fmaf(h0.y, a1v.y, c1v.y) + acc[mt][nt][1] + fbv.y) * a2v.y + c2v.y;
            o1.x = (fmaf(h1.x, a1v.x, c1v.x) + acc[mt][nt][2] + fbv.x) * a2v.x + c2v.x;
            o1.y = (fmaf(h1.y, a1v.y, c1v.y) + acc[mt][nt][3] + fbv.y) * a2v.y + c2v.y;
            *(float2*)(out + (size_t)r0 * DIM + col) = o0;
            *(float2*)(out + (size_t)(r0 + 8) * DIM + col) = o1;
        }
    }
}

extern "C" void kernel_launch(void* const* d_in, const int* in_sizes, int n_in,
                              void* d_out, int out_size) {
    // metadata order: A,h,qw,qb,kw,kb,vw,vb,ow,ob,f1w,f1b,f2w,f2b,bn1_*,bn2_*
    const float* h   = (const float*)d_in[1];
    const float* vw  = (const float*)d_in[6];
    const float* vb  = (const float*)d_in[7];
    const float* ow  = (const float*)d_in[8];
    const float* ob  = (const float*)d_in[9];
    const float* f1w = (const float*)d_in[10];
    const float* f1b = (const float*)d_in[11];
    const float* f2w = (const float*)d_in[12];
    const float* f2b = (const float*)d_in[13];
    const float* b1g = (const float*)d_in[14];
    const float* b1b = (const float*)d_in[15];
    const float* b1m = (const float*)d_in[16];
    const float* b1v = (const float*)d_in[17];
    const float* b2g = (const float*)d_in[18];
    const float* b2b = (const float*)d_in[19];
    const float* b2m = (const float*)d_in[20];
    const float* b2v = (const float*)d_in[21];
    float* out = (float*)d_out;

    cudaFuncSetAttribute(ffn1_kernel, cudaFuncAttributeMaxDynamicSharedMemorySize, 98304);
    cudaFuncSetAttribute(ffn2_kernel, cudaFuncAttributeMaxDynamicSharedMemorySize, 98304);

    colsum_kernel<<<128, 512>>>(h);
    prep1_kernel<<<2, 256>>>(vw, vb);
    prep2_kernel<<<2, 256>>>(ow, ob, b1g, b1b, b1m, b1v, b2g, b2b, b2m, b2v);
    prep_x1_frag<<<1024, 256>>>(h);
    wfrag_kernel<<<128, 256>>>(f1w, DIM, HID, 0);   // -> g_w1f
    wfrag_kernel<<<128, 256>>>(f2w, HID, DIM, 1);   // -> g_w2f
    dim3 g1(HID / 128, NROWS / 128);   // (8, 64)
    ffn1_kernel<<<g1, 128, 98304>>>(f1b);
    dim3 g2(DIM / 128, NROWS / 128);   // (4, 64)
    ffn2_kernel<<<g2, 128, 98304>>>(h, f2b, out);
}

// round 13
// speedup vs baseline: 1.1784x; 1.0034x over previous
#include <cuda_runtime.h>

#define NROWS 8192
#define DIM   512
#define HID   1024

// Scratch (allocation-free __device__ globals), 16B-aligned.
// RULE 1 (GB300/ATS trap): NEVER pass these as kernel args from host code.
// RULE 2 (build trap): harness lowers via compute_103 PTX — tcgen05/TMEM
// instructions DO NOT COMPILE. mma.sync only.
__device__ __align__(16) float g_part[128 * DIM];
__device__ __align__(16) float g_s[DIM];
__device__ __align__(16) float g_a1[DIM], g_c1[DIM];
__device__ __align__(16) float g_a2[DIM], g_c2[DIM];
// Fragment-ordered operands (VALIDATED R10/R11, fingerprint 9.342721e-05):
// A-frag tile (128m x 32k): idx = ((kstep<<3)+mtile)*128 + l*4 + j
//   kstep=cc>>3, mtile=row>>4, l=((row&7)<<2)|(cc&3), j=(((cc>>2)&1)<<1)|((row>>3)&1)
// B-frag tile (128n x 32k): idx = ((kstep<<4)+ntile)*64 + l*2 + j
//   ntile=n>>3, l=((n&7)<<2)|(k&3), j=(k>>2)&1
__device__ __align__(16) float g_x1f[(size_t)NROWS * DIM];   // [mb(64)][kb(16)][4096]
__device__ __align__(16) float g_yf[(size_t)NROWS * HID];    // [mb(64)][kb(32)][4096]
__device__ __align__(16) float g_w1f[(size_t)HID * DIM];     // [nb(8)][kb(16)][4096]
__device__ __align__(16) float g_w2f[(size_t)DIM * HID];     // [nb(4)][kb(32)][4096]

// ---------------- helpers ----------------
__device__ __forceinline__ unsigned tf32r(float x) {
    unsigned r;
    asm("cvt.rna.tf32.f32 %0, %1;" : "=r"(r) : "f"(x));
    return r;
}
__device__ __forceinline__ void mma_tf32(float* d, const unsigned* a, const unsigned* b) {
    asm volatile(
        "mma.sync.aligned.m16n8k8.row.col.f32.tf32.tf32.f32 "
        "{%0,%1,%2,%3}, {%4,%5,%6,%7}, {%8,%9}, {%0,%1,%2,%3};"
        : "+f"(d[0]), "+f"(d[1]), "+f"(d[2]), "+f"(d[3])
        : "r"(a[0]), "r"(a[1]), "r"(a[2]), "r"(a[3]), "r"(b[0]), "r"(b[1]));
}
__device__ __forceinline__ void cp16(unsigned dst, const void* src) {
    asm volatile("cp.async.cg.shared.global [%0], [%1], 16;" :: "r"(dst), "l"(src));
}
#define CP_COMMIT()  asm volatile("cp.async.commit_group;")
#define CP_WAIT1()   asm volatile("cp.async.wait_group 1;" ::: "memory")
#define CP_WAIT0()   asm volatile("cp.async.wait_group 0;" ::: "memory")

// ---------------- stage 1: column partial sums of h ----------------
__global__ void colsum_kernel(const float* __restrict__ h) {
    int d  = threadIdx.x;
    int r0 = blockIdx.x * 64;
    float s = 0.f;
#pragma unroll 8
    for (int r = 0; r < 64; r++)
        s += h[(size_t)(r0 + r) * DIM + d];
    g_part[blockIdx.x * DIM + d] = s;
}

// ---------------- stage 2: s = colsum(h)@vw + N*vb ----------------
__global__ void prep1_kernel(const float* __restrict__ vw,
                             const float* __restrict__ vb) {
    __shared__ float hs[DIM];
    for (int i = threadIdx.x; i < DIM; i += blockDim.x) {
        float s = 0.f;
#pragma unroll 8
        for (int b = 0; b < 128; b++) s += g_part[b * DIM + i];
        hs[i] = s;
    }
    __syncthreads();
    int d = blockIdx.x * blockDim.x + threadIdx.x;
    float s = 0.f;
#pragma unroll 8
    for (int k = 0; k < DIM; k++) s = fmaf(hs[k], vw[k * DIM + d], s);
    g_s[d] = s + 8192.0f * vb[d];
}

// ---------------- stage 3: t = s@ow+ob; fold bn affines ----------------
__global__ void prep2_kernel(const float* __restrict__ ow, const float* __restrict__ ob,
                             const float* __restrict__ g1, const float* __restrict__ b1,
                             const float* __restrict__ m1, const float* __restrict__ v1,
                             const float* __restrict__ g2, const float* __restrict__ b2,
                             const float* __restrict__ m2, const float* __restrict__ v2) {
    __shared__ float ss[DIM];
    for (int i = threadIdx.x; i < DIM; i += blockDim.x) ss[i] = g_s[i];
    __syncthreads();
    int d = blockIdx.x * blockDim.x + threadIdx.x;
    float t = 0.f;
#pragma unroll 8
    for (int k = 0; k < DIM; k++) t = fmaf(ss[k], ow[k * DIM + d], t);
    t += ob[d];
    float A1 = g1[d] * rsqrtf(v1[d] + 1e-5f);
    g_a1[d] = A1;
    g_c1[d] = (t - m1[d]) * A1 + b1[d];
    float A2 = g2[d] * rsqrtf(v2[d] + 1e-5f);
    g_a2[d] = A2;
    g_c2[d] = b2[d] - m2[d] * A2;
}

// ---------------- prep: h -> x1 frag tiles (bn1 affine + tf32) ----------------
__global__ void prep_x1_frag(const float* __restrict__ h) {
    int mb = blockIdx.x >> 4, kb = blockIdx.x & 15;
    int tid = threadIdx.x, l = tid & 31, w = tid >> 5;
    float* tile = g_x1f + ((size_t)blockIdx.x << 12);
#pragma unroll
    for (int si = 0; si < 4; si++) {
        int s = w + si * 8;                  // 0..31 = (kstep<<3)+mtile
        int kstep = s >> 3, mtile = s & 7;
        unsigned vj[4];
#pragma unroll
        for (int j = 0; j < 4; j++) {
            int row = mtile * 16 + ((j & 1) << 3) + (l >> 2);
            int cc  = kstep * 8 + ((j >> 1) << 2) + (l & 3);
            int m = mb * 128 + row, k = kb * 32 + cc;
            vj[j] = tf32r(fmaf(h[(size_t)m * DIM + k], g_a1[k], g_c1[k]));
        }
        uint4 o; o.x = vj[0]; o.y = vj[1]; o.z = vj[2]; o.w = vj[3];
        *(uint4*)(tile + s * 128 + l * 4) = o;
    }
}

// ---------------- prep: weight [K][N] -> B frag tiles [nb][kb] (tf32) --------
// which=0 -> g_w1f; which=1 -> g_w2f. Destination selected IN DEVICE CODE.
__global__ void wfrag_kernel(const float* __restrict__ src, int K, int N, int which) {
    float* dstbase = which ? g_w2f : g_w1f;
    int KB = K >> 5;
    int nb = blockIdx.x / KB, kb = blockIdx.x % KB;
    int tid = threadIdx.x, l = tid & 31, w = tid >> 5;
    float* tile = dstbase + ((size_t)blockIdx.x << 12);
#pragma unroll
    for (int si = 0; si < 8; si++) {
        int s = w + si * 8;                  // 0..63 = (kstep<<4)+ntile
        int kstep = s >> 4, ntile = s & 15;
        unsigned vj[2];
#pragma unroll
        for (int j = 0; j < 2; j++) {
            int n  = nb * 128 + ntile * 8 + (l >> 2);
            int k  = kb * 32 + kstep * 8 + (j << 2) + (l & 3);
            vj[j] = tf32r(src[(size_t)k * N + n]);
        }
        uint2 o; o.x = vj[0]; o.y = vj[1];
        *(uint2*)(tile + s * 64 + l * 2) = o;
    }
}

// =====================================================================
// 2-stage cp.async tf32 GEMM, 64x64 warp tiles (R11 skeleton, depth 3->2).
// CTA 128x128, BK=32, 128 threads = 4 warps (2x2), warp tile 64x64.
// Stage = A 16KB + B 16KB; 2 stages = 64KB dynamic smem -> 3 CTAs/SM.
// =====================================================================
#define STAGE_CP(st, kb, Abase, Bbase)                                        \
    {                                                                         \
        unsigned sb = smem_base + (unsigned)(st) * 32768u;                    \
        const float* at = (Abase) + ((size_t)(kb) << 12);                     \
        const float* bt = (Bbase) + ((size_t)(kb) << 12);                     \
        _Pragma("unroll")                                                     \
        for (int i = 0; i < 8; i++) {                                         \
            int ch = tid + i * 128;                                           \
            cp16(sb + ch * 16, at + ch * 4);                                  \
            cp16(sb + 16384u + ch * 16, bt + ch * 4);                         \
        }                                                                     \
    }

#define COMPUTE_ST(st)                                                        \
    {                                                                         \
        const unsigned* As = dsm_u + (unsigned)(st) * 8192u;                  \
        const unsigned* Bs = As + 4096u;                                      \
        _Pragma("unroll")                                                     \
        for (int ks = 0; ks < 4; ks++) {                                      \
            unsigned af[4][4], bf[8][2];                                      \
            _Pragma("unroll")                                                 \
            for (int mt = 0; mt < 4; mt++) {                                  \
                uint4 v = *(const uint4*)&As[((ks << 3) + w_m * 4 + mt) * 128 \
                                             + lane * 4];                     \
                af[mt][0] = v.x; af[mt][1] = v.y;                             \
                af[mt][2] = v.z; af[mt][3] = v.w;                             \
            }                                                                 \
            _Pragma("unroll")                                                 \
            for (int nt = 0; nt < 8; nt++) {                                  \
                uint2 v = *(const uint2*)&Bs[((ks << 4) + w_n * 8 + nt) * 64  \
                                             + lane * 2];                     \
                bf[nt][0] = v.x; bf[nt][1] = v.y;                             \
            }                                                                 \
            _Pragma("unroll")                                                 \
            for (int mt = 0; mt < 4; mt++)                                    \
                _Pragma("unroll")                                             \
                for (int nt = 0; nt < 8; nt++)                                \
                    mma_tf32(acc[mt][nt], af[mt], bf[nt]);                    \
        }                                                                     \
    }

#define GEMM_PRE()                                                            \
    extern __shared__ unsigned dsm_u[];                                       \
    unsigned smem_base = (unsigned)__cvta_generic_to_shared(dsm_u);           \
    const int tid = threadIdx.x;                                              \
    const int lane = tid & 31, wid = tid >> 5;                                \
    const int w_m = wid & 1, w_n = wid >> 1;                                  \
    const int g = lane >> 2, tg = lane & 3;                                   \
    float acc[4][8][4];                                                       \
    _Pragma("unroll")                                                         \
    for (int mt = 0; mt < 4; mt++)                                            \
        _Pragma("unroll")                                                     \
        for (int nt = 0; nt < 8; nt++)                                        \
            _Pragma("unroll")                                                 \
            for (int q = 0; q < 4; q++) acc[mt][nt][q] = 0.f;

// 2-stage ping-pong: stage kb+1 while computing kb. Trailing sync protects
// buffer (kb&1) from being overwritten by iteration kb+1's staging of kb+2.
#define GEMM_MAINLOOP(Abase, Bbase, KBT)                                      \
    {                                                                         \
        STAGE_CP(0, 0, Abase, Bbase); CP_COMMIT();                            \
        _Pragma("unroll 1")                                                   \
        for (int kb = 0; kb < (KBT); kb++) {                                  \
            if (kb + 1 < (KBT)) {                                             \
                STAGE_CP((kb + 1) & 1, kb + 1, Abase, Bbase); CP_COMMIT();    \
                CP_WAIT1();                                                   \
            } else {                                                          \
                CP_WAIT0();                                                   \
            }                                                                 \
            __syncthreads();                                                  \
            COMPUTE_ST(kb & 1);                                               \
            __syncthreads();                                                  \
        }                                                                     \
    }

// ---------------- FFN GEMM 1: yf = tf32(relu(x1 @ w1 + f1b)) (frag store) ----
__global__ __launch_bounds__(128) void ffn1_kernel(const float* __restrict__ bias) {
    GEMM_PRE();
    const float* Ab = g_x1f + (((size_t)blockIdx.y * 16) << 12);   // mb*16 tiles
    const float* Bb = g_w1f + (((size_t)blockIdx.x * 16) << 12);   // nb*16 tiles
    GEMM_MAINLOOP(Ab, Bb, 16);
    const int bn = blockIdx.x * 128;
#pragma unroll
    for (int mt = 0; mt < 4; mt++)
#pragma unroll
        for (int nt = 0; nt < 8; nt++) {
            int col0 = bn + w_n * 64 + nt * 8 + 2 * tg;
            float b0 = bias[col0], b1 = bias[col0 + 1];
#pragma unroll
            for (int q = 0; q < 4; q++) {
                int row = w_m * 64 + mt * 16 + g + ((q >> 1) << 3); // local m
                int col = col0 + (q & 1);                            // global k
                float v = fmaxf(acc[mt][nt][q] + ((q & 1) ? b1 : b0), 0.f);
                int kb = col >> 5, cc = col & 31;
                int kstep = cc >> 3, mtile = row >> 4;
                int l = ((row & 7) << 2) | (cc & 3);
                int j = (((cc >> 2) & 1) << 1) | ((row >> 3) & 1);
                g_yf[(((size_t)blockIdx.y * 32 + kb) << 12) +
                     ((kstep << 3) + mtile) * 128 + l * 4 + j] =
                    __uint_as_float(tf32r(v));
            }
        }
}

// ---------------- FFN GEMM 2 + residual + bn2 (row-major out) ----------------
__global__ __launch_bounds__(128) void ffn2_kernel(
    const float* __restrict__ h, const float* __restrict__ bias,
    float* __restrict__ out) {
    GEMM_PRE();
    const float* Ab = g_yf  + (((size_t)blockIdx.y * 32) << 12);   // mb*32 tiles
    const float* Bb = g_w2f + (((size_t)blockIdx.x * 32) << 12);   // nb*32 tiles
    GEMM_MAINLOOP(Ab, Bb, 32);
    const int bm = blockIdx.y * 128;
    const int bn = blockIdx.x * 128;
#pragma unroll
    for (int nt = 0; nt < 8; nt++) {
        int col = bn + w_n * 64 + nt * 8 + 2 * tg;
        float2 fbv = *(const float2*)(bias + col);
        float2 a1v = *(const float2*)(g_a1 + col);
        float2 c1v = *(const float2*)(g_c1 + col);
        float2 a2v = *(const float2*)(g_a2 + col);
        float2 c2v = *(const float2*)(g_c2 + col);
#pragma unroll
        for (int mt = 0; mt < 4; mt++) {
            int r0 = bm + w_m * 64 + mt * 16 + g;
            float2 h0 = *(const float2*)(h + (size_t)r0 * DIM + col);
            float2 h1 = *(const float2*)(h + (size_t)(r0 + 8) * DIM + col);
            float2 o0, o1;
            o0.x = (fmaf(h0.x, a1v.x, c1v.x) + acc[mt][nt][0] + fbv.x) * a2v.x + c2v.x;
            o0.y = (fmaf(h0.y, a1v.y, c1v.y) + acc[mt][nt][1] + fbv.y) * a2v.y + c2v.y;
            o1.x = (fmaf(h1.x, a1v.x, c1v.x) + acc[mt][nt][2] + fbv.x) * a2v.x + c2v.x;
            o1.y = (fmaf(h1.y, a1v.y, c1v.y) + acc[mt][nt][3] + fbv.y) * a2v.y + c2v.y;
            *(float2*)(out + (size_t)r0 * DIM + col) = o0;
            *(float2*)(out + (size_t)(r0 + 8) * DIM + col) = o1;
        }
    }
}

extern "C" void kernel_launch(void* const* d_in, const int* in_sizes, int n_in,
                              void* d_out, int out_size) {
    // metadata order: A,h,qw,qb,kw,kb,vw,vb,ow,ob,f1w,f1b,f2w,f2b,bn1_*,bn2_*
    const float* h   = (const float*)d_in[1];
    const float* vw  = (const float*)d_in[6];
    const float* vb  = (const float*)d_in[7];
    const float* ow  = (const float*)d_in[8];
    const float* ob  = (const float*)d_in[9];
    const float* f1w = (const float*)d_in[10];
    const float* f1b = (const float*)d_in[11];
    const float* f2w = (const float*)d_in[12];
    const float* f2b = (const float*)d_in[13];
    const float* b1g = (const float*)d_in[14];
    const float* b1b = (const float*)d_in[15];
    const float* b1m = (const float*)d_in[16];
    const float* b1v = (const float*)d_in[17];
    const float* b2g = (const float*)d_in[18];
    const float* b2b = (const float*)d_in[19];
    const float* b2m = (const float*)d_in[20];
    const float* b2v = (const float*)d_in[21];
    float* out = (float*)d_out;

    cudaFuncSetAttribute(ffn1_kernel, cudaFuncAttributeMaxDynamicSharedMemorySize, 65536);
    cudaFuncSetAttribute(ffn2_kernel, cudaFuncAttributeMaxDynamicSharedMemorySize, 65536);

    colsum_kernel<<<128, 512>>>(h);
    prep1_kernel<<<2, 256>>>(vw, vb);
    prep2_kernel<<<2, 256>>>(ow, ob, b1g, b1b, b1m, b1v, b2g, b2b, b2m, b2v);
    prep_x1_frag<<<1024, 256>>>(h);
    wfrag_kernel<<<128, 256>>>(f1w, DIM, HID, 0);   // -> g_w1f
    wfrag_kernel<<<128, 256>>>(f2w, HID, DIM, 1);   // -> g_w2f
    dim3 g1(HID / 128, NROWS / 128);   // (8, 64)
    ffn1_kernel<<<g1, 128, 65536>>>(f1b);
    dim3 g2(DIM / 128, NROWS / 128);   // (4, 64)
    ffn2_kernel<<<g2, 128, 65536>>>(h, f2b, out);
}